// round 1
// baseline (speedup 1.0000x reference)
#include <cuda_runtime.h>
#include <cuda_bf16.h>
#include <cstdint>

#define BB 4
#define HH 4
#define NN 2048
#define DD 64
#define BM 64
#define BN 64
#define PAD 68                      // smem row stride (floats), conflict-free frag loads
#define SCALE 0.18033688011112042f  // (1/8) * log2(e)
#define NEGBIG -1.0e30f

static const size_t ATT_OFF = (size_t)BB * HH * NN * DD;   // 2,097,152

__device__ __forceinline__ float ex2f_(float x) {
    float y;
    asm("ex2.approx.ftz.f32 %0, %1;" : "=f"(y) : "f"(x));
    return y;
}

__device__ __forceinline__ unsigned cvt_tf32(float x) {
    unsigned y;
    asm("cvt.rna.tf32.f32 %0, %1;" : "=r"(y) : "f"(x));
    return y;
}

__device__ __forceinline__ void mma_tf32(float c[4],
                                         unsigned a0, unsigned a1, unsigned a2, unsigned a3,
                                         unsigned b0, unsigned b1) {
    asm volatile(
        "mma.sync.aligned.m16n8k8.row.col.f32.tf32.tf32.f32 "
        "{%0,%1,%2,%3}, {%4,%5,%6,%7}, {%8,%9}, {%0,%1,%2,%3};"
        : "+f"(c[0]), "+f"(c[1]), "+f"(c[2]), "+f"(c[3])
        : "r"(a0), "r"(a1), "r"(a2), "r"(a3), "r"(b0), "r"(b1));
}

// Load a 64x64 fp32 tile -> smem (PAD stride), converting to tf32 bits, optional scale.
__device__ __forceinline__ void load_tile(float* dst, const float* src, int tid, float scale) {
#pragma unroll
    for (int it = 0; it < 4; ++it) {
        int idx = tid + it * 256;         // 0..1023 float4s
        int r = idx >> 4;
        int c4 = (idx & 15) << 2;
        float4 t = *(const float4*)(src + r * DD + c4);
        uint4 u;
        u.x = cvt_tf32(t.x * scale);
        u.y = cvt_tf32(t.y * scale);
        u.z = cvt_tf32(t.z * scale);
        u.w = cvt_tf32(t.w * scale);
        *(uint4*)(dst + r * PAD + c4) = u;
    }
}

// Compute the 64x64 S tile for this warp: 16 accumulators (4 n-subtiles x 4),
// then add the mask addend per column.
__device__ __forceinline__ void compute_S(const float* Qs, const float* Ks, const float* madd,
                                          int wm, int wn, int g, int tig, float c[4][4]) {
#pragma unroll
    for (int nt = 0; nt < 4; ++nt)
#pragma unroll
        for (int i = 0; i < 4; ++i) c[nt][i] = 0.f;

#pragma unroll
    for (int ks = 0; ks < 8; ++ks) {
        int db = ks * 8;
        const float* qrow = Qs + (wm * 16 + g) * PAD + db;
        unsigned a0 = __float_as_uint(qrow[tig]);
        unsigned a1 = __float_as_uint(qrow[8 * PAD + tig]);
        unsigned a2 = __float_as_uint(qrow[tig + 4]);
        unsigned a3 = __float_as_uint(qrow[8 * PAD + tig + 4]);
#pragma unroll
        for (int nt = 0; nt < 4; ++nt) {
            int jb = wn * 32 + nt * 8 + g;
            unsigned b0 = __float_as_uint(Ks[jb * PAD + db + tig]);
            unsigned b1 = __float_as_uint(Ks[jb * PAD + db + tig + 4]);
            mma_tf32(c[nt], a0, a1, a2, a3, b0, b1);
        }
    }
#pragma unroll
    for (int nt = 0; nt < 4; ++nt) {
        int col = wn * 32 + nt * 8 + tig * 2;
        float ma = madd[col];
        float mb = madd[col + 1];
        c[nt][0] += ma;
        c[nt][1] += mb;
        c[nt][2] += ma;
        c[nt][3] += mb;
    }
}

__global__ void __launch_bounds__(256)
lg_attn_kernel(const float* __restrict__ q, const float* __restrict__ k,
               const float* __restrict__ v, const int* __restrict__ mask,
               float* __restrict__ out) {
    extern __shared__ float smem[];
    float* Qs = smem;                 // 64*PAD
    float* Ks = Qs + BM * PAD;        // 64*PAD
    float* Vs = Ks + BN * PAD;        // 64*PAD
    float* Ps = Vs + BN * PAD;        // 64*PAD
    float* madd = Ps + BM * PAD;      // 64
    float* pm = madd + 64;            // [2][64]
    float* pl = pm + 128;             // [2][64]
    float* fm = pl + 128;             // 64
    float* frl = fm + 64;             // 64

    const int tid = threadIdx.x;
    const int warp = tid >> 5, lane = tid & 31;
    const int wm = warp & 3, wn = warp >> 2;
    const int g = lane >> 2, tig = lane & 3;

    const int bh = blockIdx.y;
    const int b = bh >> 2;            // H = 4
    const int i0 = blockIdx.x * BM;

    const float* qg = q + ((size_t)bh * NN + i0) * DD;
    const float* kg = k + (size_t)bh * NN * DD;
    const float* vg = v + (size_t)bh * NN * DD;
    const int* mg = mask + (size_t)b * NN;

    // Q tile: scaled by 1/sqrt(D) * log2(e) so scores are already base-2 logits.
    load_tile(Qs, qg, tid, SCALE);

    // ---------------- Pass A: online (m, l) stats, fully register-local ----------------
    float m0 = NEGBIG, m1 = NEGBIG, l0 = 0.f, l1 = 0.f;
    float c[4][4];

    for (int jt = 0; jt < 32; ++jt) {
        int j0 = jt * BN;
        __syncthreads();
        load_tile(Ks, kg + (size_t)j0 * DD, tid, 1.f);
        if (tid < 64) madd[tid] = (mg[j0 + tid] == 0) ? NEGBIG : 0.f;
        __syncthreads();

        compute_S(Qs, Ks, madd, wm, wn, g, tig, c);

        // per-thread online softmax update (row g: c[nt][0..1], row g+8: c[nt][2..3])
        float v0 = c[0][0], v1 = c[0][2];
#pragma unroll
        for (int nt = 0; nt < 4; ++nt) {
            v0 = fmaxf(v0, fmaxf(c[nt][0], c[nt][1]));
            v1 = fmaxf(v1, fmaxf(c[nt][2], c[nt][3]));
        }
        float mn0 = fmaxf(m0, v0);
        float mn1 = fmaxf(m1, v1);
        float s0 = l0 * ex2f_(m0 - mn0);
        float s1 = l1 * ex2f_(m1 - mn1);
#pragma unroll
        for (int nt = 0; nt < 4; ++nt) {
            s0 += ex2f_(c[nt][0] - mn0) + ex2f_(c[nt][1] - mn0);
            s1 += ex2f_(c[nt][2] - mn1) + ex2f_(c[nt][3] - mn1);
        }
        m0 = mn0; l0 = s0;
        m1 = mn1; l1 = s1;
    }

    // merge stats across the 4 lanes that share each row
#pragma unroll
    for (int off = 1; off <= 2; off <<= 1) {
        float mo = __shfl_xor_sync(0xffffffffu, m0, off);
        float lo = __shfl_xor_sync(0xffffffffu, l0, off);
        float mn = fmaxf(m0, mo);
        l0 = l0 * ex2f_(m0 - mn) + lo * ex2f_(mo - mn);
        m0 = mn;
        mo = __shfl_xor_sync(0xffffffffu, m1, off);
        lo = __shfl_xor_sync(0xffffffffu, l1, off);
        mn = fmaxf(m1, mo);
        l1 = l1 * ex2f_(m1 - mn) + lo * ex2f_(mo - mn);
        m1 = mn;
    }
    if (tig == 0) {
        int r0 = wm * 16 + g;
        pm[wn * 64 + r0] = m0;
        pl[wn * 64 + r0] = l0;
        pm[wn * 64 + r0 + 8] = m1;
        pl[wn * 64 + r0 + 8] = l1;
    }
    __syncthreads();
    if (tid < 64) {
        float ma = pm[tid], la = pl[tid];
        float mb = pm[64 + tid], lb = pl[64 + tid];
        float mn = fmaxf(ma, mb);
        float l = la * ex2f_(ma - mn) + lb * ex2f_(mb - mn);
        fm[tid] = mn;
        frl[tid] = 1.f / l;
    }
    __syncthreads();

    const float rm0 = fm[wm * 16 + g], rr0 = frl[wm * 16 + g];
    const float rm1 = fm[wm * 16 + g + 8], rr1 = frl[wm * 16 + g + 8];

    // ---------------- Pass B: P = softmax, write attention, O += P*V ----------------
    float o[4][4];
#pragma unroll
    for (int nt = 0; nt < 4; ++nt)
#pragma unroll
        for (int i = 0; i < 4; ++i) o[nt][i] = 0.f;

    for (int jt = 0; jt < 32; ++jt) {
        int j0 = jt * BN;
        __syncthreads();
        load_tile(Ks, kg + (size_t)j0 * DD, tid, 1.f);
        load_tile(Vs, vg + (size_t)j0 * DD, tid, 1.f);
        if (tid < 64) madd[tid] = (mg[j0 + tid] == 0) ? NEGBIG : 0.f;
        __syncthreads();

        compute_S(Qs, Ks, madd, wm, wn, g, tig, c);

        // normalize to probabilities and stage into Ps
#pragma unroll
        for (int nt = 0; nt < 4; ++nt) {
            c[nt][0] = ex2f_(c[nt][0] - rm0) * rr0;
            c[nt][1] = ex2f_(c[nt][1] - rm0) * rr0;
            c[nt][2] = ex2f_(c[nt][2] - rm1) * rr1;
            c[nt][3] = ex2f_(c[nt][3] - rm1) * rr1;
            int pr = wm * 16 + g;
            int pc = wn * 32 + nt * 8 + tig * 2;
            *(float2*)(Ps + pr * PAD + pc) = make_float2(c[nt][0], c[nt][1]);
            *(float2*)(Ps + (pr + 8) * PAD + pc) = make_float2(c[nt][2], c[nt][3]);
        }
        __syncthreads();

        // coalesced attention write (full 256B rows)
        float* abase = out + ATT_OFF + ((size_t)bh * NN + i0) * NN + j0;
#pragma unroll
        for (int it = 0; it < 4; ++it) {
            int idx = tid + it * 256;
            int r = idx >> 4;
            int c4 = (idx & 15) << 2;
            *(float4*)(abase + (size_t)r * NN + c4) = *(float4*)(Ps + r * PAD + c4);
        }

        // O += P * V  (k-dim = 64 tile columns)
#pragma unroll
        for (int ks = 0; ks < 8; ++ks) {
            int kb = ks * 8;
            const float* prow = Ps + (wm * 16 + g) * PAD + kb;
            unsigned a0 = cvt_tf32(prow[tig]);
            unsigned a1 = cvt_tf32(prow[8 * PAD + tig]);
            unsigned a2 = cvt_tf32(prow[tig + 4]);
            unsigned a3 = cvt_tf32(prow[8 * PAD + tig + 4]);
#pragma unroll
            for (int nt = 0; nt < 4; ++nt) {
                int dcol = wn * 32 + nt * 8 + g;
                unsigned b0 = __float_as_uint(Vs[(kb + tig) * PAD + dcol]);
                unsigned b1 = __float_as_uint(Vs[(kb + tig + 4) * PAD + dcol]);
                mma_tf32(o[nt], a0, a1, a2, a3, b0, b1);
            }
        }
    }

    // write O
    int orow = i0 + wm * 16 + g;
#pragma unroll
    for (int nt = 0; nt < 4; ++nt) {
        int oc = wn * 32 + nt * 8 + tig * 2;
        *(float2*)(out + ((size_t)bh * NN + orow) * DD + oc) = make_float2(o[nt][0], o[nt][1]);
        *(float2*)(out + ((size_t)bh * NN + orow + 8) * DD + oc) = make_float2(o[nt][2], o[nt][3]);
    }
}

extern "C" void kernel_launch(void* const* d_in, const int* in_sizes, int n_in,
                              void* d_out, int out_size) {
    const float* q = (const float*)d_in[0];
    const float* k = (const float*)d_in[1];
    const float* v = (const float*)d_in[2];
    const int* mask = (const int*)d_in[3];
    float* out = (float*)d_out;

    const int smem_floats = 4 * BM * PAD + 64 + 128 + 128 + 64 + 64;
    const int smem_bytes = smem_floats * (int)sizeof(float);  // 71,424 B

    cudaFuncSetAttribute(lg_attn_kernel, cudaFuncAttributeMaxDynamicSharedMemorySize, smem_bytes);

    dim3 grid(NN / BM, BB * HH);
    lg_attn_kernel<<<grid, 256, smem_bytes>>>(q, k, v, mask, out);
}

// round 2
// speedup vs baseline: 1.0005x; 1.0005x over previous
#include <cuda_runtime.h>
#include <cuda_bf16.h>
#include <cstdint>

#define BB 4
#define HH 4
#define NN 2048
#define DD 64
#define BM 64
#define BN 64
#define PAD 68                      // smem row stride (floats), conflict-free frag loads
#define SCALE 0.18033688011112042f  // (1/8) * log2(e)
#define NEGBIG -1.0e30f

static const size_t ATT_OFF = (size_t)BB * HH * NN * DD;   // 2,097,152

__device__ __forceinline__ float ex2f_(float x) {
    float y;
    asm("ex2.approx.ftz.f32 %0, %1;" : "=f"(y) : "f"(x));
    return y;
}

__device__ __forceinline__ unsigned cvt_tf32(float x) {
    unsigned y;
    asm("cvt.rna.tf32.f32 %0, %1;" : "=r"(y) : "f"(x));
    return y;
}

__device__ __forceinline__ void mma_tf32(float c[4],
                                         unsigned a0, unsigned a1, unsigned a2, unsigned a3,
                                         unsigned b0, unsigned b1) {
    asm volatile(
        "mma.sync.aligned.m16n8k8.row.col.f32.tf32.tf32.f32 "
        "{%0,%1,%2,%3}, {%4,%5,%6,%7}, {%8,%9}, {%0,%1,%2,%3};"
        : "+f"(c[0]), "+f"(c[1]), "+f"(c[2]), "+f"(c[3])
        : "r"(a0), "r"(a1), "r"(a2), "r"(a3), "r"(b0), "r"(b1));
}

// Load a 64x64 fp32 tile -> smem (PAD stride), converting to tf32 bits, optional scale.
__device__ __forceinline__ void load_tile(float* dst, const float* src, int tid, float scale) {
#pragma unroll
    for (int it = 0; it < 4; ++it) {
        int idx = tid + it * 256;         // 0..1023 float4s
        int r = idx >> 4;
        int c4 = (idx & 15) << 2;
        float4 t = *(const float4*)(src + r * DD + c4);
        uint4 u;
        u.x = cvt_tf32(t.x * scale);
        u.y = cvt_tf32(t.y * scale);
        u.z = cvt_tf32(t.z * scale);
        u.w = cvt_tf32(t.w * scale);
        *(uint4*)(dst + r * PAD + c4) = u;
    }
}

// Compute the 64x64 S tile for this warp: 16 accumulators (4 n-subtiles x 4),
// then add the mask addend per column.
__device__ __forceinline__ void compute_S(const float* Qs, const float* Ks, const float* madd,
                                          int wm, int wn, int g, int tig, float c[4][4]) {
#pragma unroll
    for (int nt = 0; nt < 4; ++nt)
#pragma unroll
        for (int i = 0; i < 4; ++i) c[nt][i] = 0.f;

#pragma unroll
    for (int ks = 0; ks < 8; ++ks) {
        int db = ks * 8;
        const float* qrow = Qs + (wm * 16 + g) * PAD + db;
        unsigned a0 = __float_as_uint(qrow[tig]);
        unsigned a1 = __float_as_uint(qrow[8 * PAD + tig]);
        unsigned a2 = __float_as_uint(qrow[tig + 4]);
        unsigned a3 = __float_as_uint(qrow[8 * PAD + tig + 4]);
#pragma unroll
        for (int nt = 0; nt < 4; ++nt) {
            int jb = wn * 32 + nt * 8 + g;
            unsigned b0 = __float_as_uint(Ks[jb * PAD + db + tig]);
            unsigned b1 = __float_as_uint(Ks[jb * PAD + db + tig + 4]);
            mma_tf32(c[nt], a0, a1, a2, a3, b0, b1);
        }
    }
#pragma unroll
    for (int nt = 0; nt < 4; ++nt) {
        int col = wn * 32 + nt * 8 + tig * 2;
        float ma = madd[col];
        float mb = madd[col + 1];
        c[nt][0] += ma;
        c[nt][1] += mb;
        c[nt][2] += ma;
        c[nt][3] += mb;
    }
}

__global__ void __launch_bounds__(256)
lg_attn_kernel(const float* __restrict__ q, const float* __restrict__ k,
               const float* __restrict__ v, const int* __restrict__ mask,
               float* __restrict__ out) {
    extern __shared__ float smem[];
    float* Qs = smem;                 // 64*PAD
    float* Ks = Qs + BM * PAD;        // 64*PAD
    float* Vs = Ks + BN * PAD;        // 64*PAD
    float* Ps = Vs + BN * PAD;        // 64*PAD
    float* madd = Ps + BM * PAD;      // 64
    float* pm = madd + 64;            // [2][64]
    float* pl = pm + 128;             // [2][64]
    float* fm = pl + 128;             // 64
    float* frl = fm + 64;             // 64

    const int tid = threadIdx.x;
    const int warp = tid >> 5, lane = tid & 31;
    const int wm = warp & 3, wn = warp >> 2;
    const int g = lane >> 2, tig = lane & 3;

    const int bh = blockIdx.y;
    const int b = bh >> 2;            // H = 4
    const int i0 = blockIdx.x * BM;

    const float* qg = q + ((size_t)bh * NN + i0) * DD;
    const float* kg = k + (size_t)bh * NN * DD;
    const float* vg = v + (size_t)bh * NN * DD;
    const int* mg = mask + (size_t)b * NN;

    // Q tile: scaled by 1/sqrt(D) * log2(e) so scores are already base-2 logits.
    load_tile(Qs, qg, tid, SCALE);

    // ---------------- Pass A: online (m, l) stats, fully register-local ----------------
    float m0 = NEGBIG, m1 = NEGBIG, l0 = 0.f, l1 = 0.f;
    float c[4][4];

    for (int jt = 0; jt < 32; ++jt) {
        int j0 = jt * BN;
        __syncthreads();
        load_tile(Ks, kg + (size_t)j0 * DD, tid, 1.f);
        if (tid < 64) madd[tid] = (mg[j0 + tid] == 0) ? NEGBIG : 0.f;
        __syncthreads();

        compute_S(Qs, Ks, madd, wm, wn, g, tig, c);

        // per-thread online softmax update (row g: c[nt][0..1], row g+8: c[nt][2..3])
        float v0 = c[0][0], v1 = c[0][2];
#pragma unroll
        for (int nt = 0; nt < 4; ++nt) {
            v0 = fmaxf(v0, fmaxf(c[nt][0], c[nt][1]));
            v1 = fmaxf(v1, fmaxf(c[nt][2], c[nt][3]));
        }
        float mn0 = fmaxf(m0, v0);
        float mn1 = fmaxf(m1, v1);
        float s0 = l0 * ex2f_(m0 - mn0);
        float s1 = l1 * ex2f_(m1 - mn1);
#pragma unroll
        for (int nt = 0; nt < 4; ++nt) {
            s0 += ex2f_(c[nt][0] - mn0) + ex2f_(c[nt][1] - mn0);
            s1 += ex2f_(c[nt][2] - mn1) + ex2f_(c[nt][3] - mn1);
        }
        m0 = mn0; l0 = s0;
        m1 = mn1; l1 = s1;
    }

    // merge stats across the 4 lanes that share each row
#pragma unroll
    for (int off = 1; off <= 2; off <<= 1) {
        float mo = __shfl_xor_sync(0xffffffffu, m0, off);
        float lo = __shfl_xor_sync(0xffffffffu, l0, off);
        float mn = fmaxf(m0, mo);
        l0 = l0 * ex2f_(m0 - mn) + lo * ex2f_(mo - mn);
        m0 = mn;
        mo = __shfl_xor_sync(0xffffffffu, m1, off);
        lo = __shfl_xor_sync(0xffffffffu, l1, off);
        mn = fmaxf(m1, mo);
        l1 = l1 * ex2f_(m1 - mn) + lo * ex2f_(mo - mn);
        m1 = mn;
    }
    if (tig == 0) {
        int r0 = wm * 16 + g;
        pm[wn * 64 + r0] = m0;
        pl[wn * 64 + r0] = l0;
        pm[wn * 64 + r0 + 8] = m1;
        pl[wn * 64 + r0 + 8] = l1;
    }
    __syncthreads();
    if (tid < 64) {
        float ma = pm[tid], la = pl[tid];
        float mb = pm[64 + tid], lb = pl[64 + tid];
        float mn = fmaxf(ma, mb);
        float l = la * ex2f_(ma - mn) + lb * ex2f_(mb - mn);
        fm[tid] = mn;
        frl[tid] = 1.f / l;
    }
    __syncthreads();

    const float rm0 = fm[wm * 16 + g], rr0 = frl[wm * 16 + g];
    const float rm1 = fm[wm * 16 + g + 8], rr1 = frl[wm * 16 + g + 8];

    // ---------------- Pass B: P = softmax, write attention, O += P*V ----------------
    float o[4][4];
#pragma unroll
    for (int nt = 0; nt < 4; ++nt)
#pragma unroll
        for (int i = 0; i < 4; ++i) o[nt][i] = 0.f;

    for (int jt = 0; jt < 32; ++jt) {
        int j0 = jt * BN;
        __syncthreads();
        load_tile(Ks, kg + (size_t)j0 * DD, tid, 1.f);
        load_tile(Vs, vg + (size_t)j0 * DD, tid, 1.f);
        if (tid < 64) madd[tid] = (mg[j0 + tid] == 0) ? NEGBIG : 0.f;
        __syncthreads();

        compute_S(Qs, Ks, madd, wm, wn, g, tig, c);

        // normalize to probabilities and stage into Ps
#pragma unroll
        for (int nt = 0; nt < 4; ++nt) {
            c[nt][0] = ex2f_(c[nt][0] - rm0) * rr0;
            c[nt][1] = ex2f_(c[nt][1] - rm0) * rr0;
            c[nt][2] = ex2f_(c[nt][2] - rm1) * rr1;
            c[nt][3] = ex2f_(c[nt][3] - rm1) * rr1;
            int pr = wm * 16 + g;
            int pc = wn * 32 + nt * 8 + tig * 2;
            *(float2*)(Ps + pr * PAD + pc) = make_float2(c[nt][0], c[nt][1]);
            *(float2*)(Ps + (pr + 8) * PAD + pc) = make_float2(c[nt][2], c[nt][3]);
        }
        __syncthreads();

        // coalesced attention write (full 256B rows)
        float* abase = out + ATT_OFF + ((size_t)bh * NN + i0) * NN + j0;
#pragma unroll
        for (int it = 0; it < 4; ++it) {
            int idx = tid + it * 256;
            int r = idx >> 4;
            int c4 = (idx & 15) << 2;
            *(float4*)(abase + (size_t)r * NN + c4) = *(float4*)(Ps + r * PAD + c4);
        }

        // O += P * V  (k-dim = 64 tile columns)
#pragma unroll
        for (int ks = 0; ks < 8; ++ks) {
            int kb = ks * 8;
            const float* prow = Ps + (wm * 16 + g) * PAD + kb;
            unsigned a0 = cvt_tf32(prow[tig]);
            unsigned a1 = cvt_tf32(prow[8 * PAD + tig]);
            unsigned a2 = cvt_tf32(prow[tig + 4]);
            unsigned a3 = cvt_tf32(prow[8 * PAD + tig + 4]);
#pragma unroll
            for (int nt = 0; nt < 4; ++nt) {
                int dcol = wn * 32 + nt * 8 + g;
                unsigned b0 = __float_as_uint(Vs[(kb + tig) * PAD + dcol]);
                unsigned b1 = __float_as_uint(Vs[(kb + tig + 4) * PAD + dcol]);
                mma_tf32(o[nt], a0, a1, a2, a3, b0, b1);
            }
        }
    }

    // write O
    int orow = i0 + wm * 16 + g;
#pragma unroll
    for (int nt = 0; nt < 4; ++nt) {
        int oc = wn * 32 + nt * 8 + tig * 2;
        *(float2*)(out + ((size_t)bh * NN + orow) * DD + oc) = make_float2(o[nt][0], o[nt][1]);
        *(float2*)(out + ((size_t)bh * NN + orow + 8) * DD + oc) = make_float2(o[nt][2], o[nt][3]);
    }
}

extern "C" void kernel_launch(void* const* d_in, const int* in_sizes, int n_in,
                              void* d_out, int out_size) {
    const float* q = (const float*)d_in[0];
    const float* k = (const float*)d_in[1];
    const float* v = (const float*)d_in[2];
    const int* mask = (const int*)d_in[3];
    float* out = (float*)d_out;

    const int smem_floats = 4 * BM * PAD + 64 + 128 + 128 + 64 + 64;
    const int smem_bytes = smem_floats * (int)sizeof(float);  // 71,424 B

    cudaFuncSetAttribute(lg_attn_kernel, cudaFuncAttributeMaxDynamicSharedMemorySize, smem_bytes);

    dim3 grid(NN / BM, BB * HH);
    lg_attn_kernel<<<grid, 256, smem_bytes>>>(q, k, v, mask, out);
}

// round 4
// speedup vs baseline: 1.3205x; 1.3198x over previous
#include <cuda_runtime.h>
#include <cstdint>

#define NSEQ 2048
#define SCALEQ 0.18033688011112042f   // (1/sqrt(64)) * log2(e)
#define NEGB (-1.0e30f)

// smem float offsets
#define QS    0        // 128 x 68
#define KS0   8704     // 64 x 68
#define KS1   13056
#define VS0   17408    // 64 x 72
#define VS1   22016
#define PS    26624    // 8 warps x (32 x 36)
#define MSK   35840    // 64 u32 mask bitwords
#define MPART 35904    // 2 x 128
#define LPART 36160    // 2 x 128
#define RMOF  36416    // 128
#define RROF  36544    // 128
#define SMEMF 36672    // floats (146,688 B)

static const size_t ATT_OFF = 2097152;   // 16*2048*64

__device__ __forceinline__ float ex2f_(float x) {
    float y; asm("ex2.approx.ftz.f32 %0, %1;" : "=f"(y) : "f"(x)); return y;
}
__device__ __forceinline__ unsigned cvt_tf32(float x) {
    unsigned y; asm("cvt.rna.tf32.f32 %0, %1;" : "=r"(y) : "f"(x)); return y;
}
__device__ __forceinline__ void mma_tf32(float c[4],
                                         unsigned a0, unsigned a1, unsigned a2, unsigned a3,
                                         unsigned b0, unsigned b1) {
    asm volatile(
        "mma.sync.aligned.m16n8k8.row.col.f32.tf32.tf32.f32 "
        "{%0,%1,%2,%3}, {%4,%5,%6,%7}, {%8,%9}, {%0,%1,%2,%3};"
        : "+f"(c[0]), "+f"(c[1]), "+f"(c[2]), "+f"(c[3])
        : "r"(a0), "r"(a1), "r"(a2), "r"(a3), "r"(b0), "r"(b1));
}

// ---- 64x64 tile LDG into registers (4 x float4 per thread) ----
__device__ __forceinline__ void ldg_tile(const float* __restrict__ src, float4 r[4], int tid) {
#pragma unroll
    for (int it = 0; it < 4; ++it) {
        int idx = tid + it * 256;
        int rr = idx >> 4, c4 = (idx & 15) << 2;
        r[it] = *(const float4*)(src + rr * 64 + c4);
    }
}
// ---- STS with tf32 convert, row stride SR floats ----
template <int SR>
__device__ __forceinline__ void sts_tile(float* dst, const float4 r[4], int tid) {
#pragma unroll
    for (int it = 0; it < 4; ++it) {
        int idx = tid + it * 256;
        int rr = idx >> 4, c4 = (idx & 15) << 2;
        uint4 u;
        u.x = cvt_tf32(r[it].x); u.y = cvt_tf32(r[it].y);
        u.z = cvt_tf32(r[it].z); u.w = cvt_tf32(r[it].w);
        *(uint4*)(dst + rr * SR + c4) = u;
    }
}

// S tile: warp (wm, wn) computes rows wm*32..+31, cols wn*32..+31 of the 128x64 S tile.
__device__ __forceinline__ void compute_S(const float* __restrict__ Qs, const float* __restrict__ Ks,
                                          int wm, int wn, int g, int tig, float c[2][4][4]) {
#pragma unroll
    for (int ms = 0; ms < 2; ++ms)
#pragma unroll
        for (int nt = 0; nt < 4; ++nt)
#pragma unroll
            for (int e = 0; e < 4; ++e) c[ms][nt][e] = 0.f;

#pragma unroll
    for (int ks = 0; ks < 8; ++ks) {
        int db = ks * 8;
        unsigned a[2][4];
#pragma unroll
        for (int ms = 0; ms < 2; ++ms) {
            const float* qr = Qs + (wm * 32 + ms * 16 + g) * 68 + db;
            a[ms][0] = __float_as_uint(qr[tig]);
            a[ms][1] = __float_as_uint(qr[8 * 68 + tig]);
            a[ms][2] = __float_as_uint(qr[tig + 4]);
            a[ms][3] = __float_as_uint(qr[8 * 68 + tig + 4]);
        }
#pragma unroll
        for (int nt = 0; nt < 4; ++nt) {
            const float* kr = Ks + (wn * 32 + nt * 8 + g) * 68 + db;
            unsigned b0 = __float_as_uint(kr[tig]);
            unsigned b1 = __float_as_uint(kr[tig + 4]);
            mma_tf32(c[0][nt], a[0][0], a[0][1], a[0][2], a[0][3], b0, b1);
            mma_tf32(c[1][nt], a[1][0], a[1][1], a[1][2], a[1][3], b0, b1);
        }
    }
}

__global__ void __launch_bounds__(256, 1)
lg2_kernel(const float* __restrict__ q, const float* __restrict__ k,
           const float* __restrict__ v, const int* __restrict__ mask,
           float* __restrict__ out) {
    extern __shared__ float sm[];
    const int tid = threadIdx.x;
    const int w = tid >> 5, lane = tid & 31;
    const int wm = w & 3, wn = w >> 2;
    const int g = lane >> 2, tig = lane & 3;

    const int bh = blockIdx.y, b = bh >> 2;     // H = 4
    const int i0 = blockIdx.x * 128;

    const float* qg = q + ((size_t)bh * NSEQ + i0) * 64;
    const float* kg = k + (size_t)bh * NSEQ * 64;
    const float* vg = v + (size_t)bh * NSEQ * 64;
    const int* mg = mask + (size_t)b * NSEQ;
    float* attg = out + ATT_OFF + ((size_t)bh * NSEQ + i0) * NSEQ;
    unsigned* mw = (unsigned*)(sm + MSK);

    // ---- prologue: Q (scaled, tf32) to smem; mask bitwords; K tile 0 ----
#pragma unroll
    for (int it = 0; it < 8; ++it) {
        int idx = tid + it * 256;
        int r = idx >> 4, c4 = (idx & 15) << 2;
        float4 t = *(const float4*)(qg + r * 64 + c4);
        uint4 u;
        u.x = cvt_tf32(t.x * SCALEQ); u.y = cvt_tf32(t.y * SCALEQ);
        u.z = cvt_tf32(t.z * SCALEQ); u.w = cvt_tf32(t.w * SCALEQ);
        *(uint4*)(sm + QS + r * 68 + c4) = u;
    }
    if (tid < 64) {
        unsigned bits = 0;
#pragma unroll 8
        for (int r = 0; r < 32; ++r) bits |= (mg[tid * 32 + r] != 0 ? 1u : 0u) << r;
        mw[tid] = bits;
    }
    {
        float4 pk[4];
        ldg_tile(kg, pk, tid);
        sts_tile<68>(sm + KS0, pk, tid);
    }
    __syncthreads();

    // slot s (0..3): row = wm*32 + (s>>1)*16 + g + (s&1)*8
    float m[4], l[4];
#pragma unroll
    for (int s = 0; s < 4; ++s) { m[s] = NEGB; l[s] = 0.f; }

    // =================== Pass A: row max / sum ===================
    for (int j = 0; j < 32; ++j) {
        float4 pk[4];
        if (j < 31) ldg_tile(kg + (size_t)(j + 1) * 64 * 64, pk, tid);

        float c[2][4][4];
        compute_S(sm + QS, sm + ((j & 1) ? KS1 : KS0), wm, wn, g, tig, c);

        unsigned bits = mw[2 * j + wn];
        float sv[2][4][4];
        float tm[4] = {NEGB, NEGB, NEGB, NEGB};
#pragma unroll
        for (int ms = 0; ms < 2; ++ms)
#pragma unroll
            for (int nt = 0; nt < 4; ++nt)
#pragma unroll
                for (int e = 0; e < 4; ++e) {
                    int bit = nt * 8 + 2 * tig + (e & 1);
                    float s = ((bits >> bit) & 1u) ? c[ms][nt][e] : NEGB;
                    sv[ms][nt][e] = s;
                    int slot = ms * 2 + (e >> 1);
                    tm[slot] = fmaxf(tm[slot], s);
                }
#pragma unroll
        for (int s = 0; s < 4; ++s) {
            float mn = fmaxf(m[s], tm[s]);
            l[s] *= ex2f_(m[s] - mn);
            m[s] = mn;
        }
#pragma unroll
        for (int ms = 0; ms < 2; ++ms)
#pragma unroll
            for (int nt = 0; nt < 4; ++nt)
#pragma unroll
                for (int e = 0; e < 4; ++e) {
                    int slot = ms * 2 + (e >> 1);
                    l[slot] += ex2f_(sv[ms][nt][e] - m[slot]);
                }

        if (j < 31) sts_tile<68>(sm + (((j + 1) & 1) ? KS1 : KS0), pk, tid);
        __syncthreads();
    }

    // merge across the 4 lanes sharing each row, then across wn halves
#pragma unroll
    for (int s = 0; s < 4; ++s) {
#pragma unroll
        for (int off = 1; off <= 2; off <<= 1) {
            float mo = __shfl_xor_sync(0xffffffffu, m[s], off);
            float lo = __shfl_xor_sync(0xffffffffu, l[s], off);
            float mn = fmaxf(m[s], mo);
            l[s] = l[s] * ex2f_(m[s] - mn) + lo * ex2f_(mo - mn);
            m[s] = mn;
        }
    }
    if (tig == 0) {
#pragma unroll
        for (int s = 0; s < 4; ++s) {
            int row = wm * 32 + (s >> 1) * 16 + g + (s & 1) * 8;
            sm[MPART + wn * 128 + row] = m[s];
            sm[LPART + wn * 128 + row] = l[s];
        }
    }
    __syncthreads();
    if (tid < 128) {
        float ma = sm[MPART + tid], mb2 = sm[MPART + 128 + tid];
        float la = sm[LPART + tid], lb2 = sm[LPART + 128 + tid];
        float mn = fmaxf(ma, mb2);
        float lt = la * ex2f_(ma - mn) + lb2 * ex2f_(mb2 - mn);
        sm[RMOF + tid] = mn;
        sm[RROF + tid] = 1.0f / lt;
    }
    __syncthreads();

    float rm[4], rri[4];
#pragma unroll
    for (int s = 0; s < 4; ++s) {
        int row = wm * 32 + (s >> 1) * 16 + g + (s & 1) * 8;
        rm[s] = sm[RMOF + row];
        rri[s] = sm[RROF + row];
    }

    // =================== Pass B: P, attention store, O += P*V ===================
    float o[2][8][4];
#pragma unroll
    for (int ms = 0; ms < 2; ++ms)
#pragma unroll
        for (int nt = 0; nt < 8; ++nt)
#pragma unroll
            for (int e = 0; e < 4; ++e) o[ms][nt][e] = 0.f;

    {
        float4 pk[4], pv[4];
        ldg_tile(kg, pk, tid);
        ldg_tile(vg, pv, tid);
        sts_tile<68>(sm + KS0, pk, tid);
        sts_tile<72>(sm + VS0, pv, tid);
    }
    __syncthreads();

    float* Pw = sm + PS + w * (32 * 36);

    for (int j = 0; j < 32; ++j) {
        float4 pk[4], pv[4];
        if (j < 31) {
            ldg_tile(kg + (size_t)(j + 1) * 64 * 64, pk, tid);
            ldg_tile(vg + (size_t)(j + 1) * 64 * 64, pv, tid);
        }

        float c[2][4][4];
        compute_S(sm + QS, sm + ((j & 1) ? KS1 : KS0), wm, wn, g, tig, c);

        unsigned bits = mw[2 * j + wn];
        float p[2][4][4];
#pragma unroll
        for (int ms = 0; ms < 2; ++ms)
#pragma unroll
            for (int nt = 0; nt < 4; ++nt)
#pragma unroll
                for (int e = 0; e < 4; ++e) {
                    int bit = nt * 8 + 2 * tig + (e & 1);
                    float s = ((bits >> bit) & 1u) ? c[ms][nt][e] : NEGB;
                    int slot = ms * 2 + (e >> 1);
                    p[ms][nt][e] = ex2f_(s - rm[slot]) * rri[slot];
                }

        // attention store straight from registers (float2 pairs)
#pragma unroll
        for (int ms = 0; ms < 2; ++ms)
#pragma unroll
            for (int nt = 0; nt < 4; ++nt) {
                int row = wm * 32 + ms * 16 + g;
                int col = j * 64 + wn * 32 + nt * 8 + 2 * tig;
                *(float2*)(attg + (size_t)row * NSEQ + col) = make_float2(p[ms][nt][0], p[ms][nt][1]);
                *(float2*)(attg + (size_t)(row + 8) * NSEQ + col) = make_float2(p[ms][nt][2], p[ms][nt][3]);
            }

        // stage P (tf32) into this warp's private smem block
#pragma unroll
        for (int ms = 0; ms < 2; ++ms)
#pragma unroll
            for (int nt = 0; nt < 4; ++nt) {
                int lr = ms * 16 + g, lc = nt * 8 + 2 * tig;
                uint2 u0 = make_uint2(cvt_tf32(p[ms][nt][0]), cvt_tf32(p[ms][nt][1]));
                uint2 u1 = make_uint2(cvt_tf32(p[ms][nt][2]), cvt_tf32(p[ms][nt][3]));
                *(uint2*)(Pw + lr * 36 + lc) = u0;
                *(uint2*)(Pw + (lr + 8) * 36 + lc) = u1;
            }
        __syncwarp();

        // O += P * V over this warp's 32 keys (split-k across wn)
        const float* Vs = sm + ((j & 1) ? VS1 : VS0);
#pragma unroll
        for (int kb = 0; kb < 4; ++kb) {
            unsigned a[2][4];
#pragma unroll
            for (int ms = 0; ms < 2; ++ms) {
                const float* pr = Pw + (ms * 16 + g) * 36 + kb * 8;
                a[ms][0] = __float_as_uint(pr[tig]);
                a[ms][1] = __float_as_uint(pr[8 * 36 + tig]);
                a[ms][2] = __float_as_uint(pr[tig + 4]);
                a[ms][3] = __float_as_uint(pr[8 * 36 + tig + 4]);
            }
            int krow = wn * 32 + kb * 8;
#pragma unroll
            for (int nt = 0; nt < 8; ++nt) {
                unsigned b0 = __float_as_uint(Vs[(krow + tig) * 72 + nt * 8 + g]);
                unsigned b1 = __float_as_uint(Vs[(krow + tig + 4) * 72 + nt * 8 + g]);
                mma_tf32(o[0][nt], a[0][0], a[0][1], a[0][2], a[0][3], b0, b1);
                mma_tf32(o[1][nt], a[1][0], a[1][1], a[1][2], a[1][3], b0, b1);
            }
        }

        if (j < 31) {
            sts_tile<68>(sm + (((j + 1) & 1) ? KS1 : KS0), pk, tid);
            sts_tile<72>(sm + (((j + 1) & 1) ? VS1 : VS0), pv, tid);
        }
        __syncthreads();
    }

    // ---- combine split-k halves of O and store ----
    __syncthreads();
    float* Os = sm + QS;   // Q region is dead now; stride 68
    if (wn == 1) {
#pragma unroll
        for (int ms = 0; ms < 2; ++ms)
#pragma unroll
            for (int nt = 0; nt < 8; ++nt) {
                int row = wm * 32 + ms * 16 + g, col = nt * 8 + 2 * tig;
                *(float2*)(Os + row * 68 + col) = make_float2(o[ms][nt][0], o[ms][nt][1]);
                *(float2*)(Os + (row + 8) * 68 + col) = make_float2(o[ms][nt][2], o[ms][nt][3]);
            }
    }
    __syncthreads();
    if (wn == 0) {
#pragma unroll
        for (int ms = 0; ms < 2; ++ms)
#pragma unroll
            for (int nt = 0; nt < 8; ++nt) {
                int row = wm * 32 + ms * 16 + g, col = nt * 8 + 2 * tig;
                float2 h0 = *(float2*)(Os + row * 68 + col);
                float2 h1 = *(float2*)(Os + (row + 8) * 68 + col);
                float* og0 = out + ((size_t)bh * NSEQ + i0 + row) * 64 + col;
                float* og1 = out + ((size_t)bh * NSEQ + i0 + row + 8) * 64 + col;
                *(float2*)og0 = make_float2(o[ms][nt][0] + h0.x, o[ms][nt][1] + h0.y);
                *(float2*)og1 = make_float2(o[ms][nt][2] + h1.x, o[ms][nt][3] + h1.y);
            }
    }
}

extern "C" void kernel_launch(void* const* d_in, const int* in_sizes, int n_in,
                              void* d_out, int out_size) {
    const float* q = (const float*)d_in[0];
    const float* k = (const float*)d_in[1];
    const float* v = (const float*)d_in[2];
    const int* mask = (const int*)d_in[3];
    float* out = (float*)d_out;

    const int smem_bytes = SMEMF * (int)sizeof(float);   // 146,688 B
    cudaFuncSetAttribute(lg2_kernel, cudaFuncAttributeMaxDynamicSharedMemorySize, smem_bytes);

    dim3 grid(NSEQ / 128, 16);
    lg2_kernel<<<grid, 256, smem_bytes>>>(q, k, v, mask, out);
}

// round 5
// speedup vs baseline: 1.3695x; 1.0372x over previous
#include <cuda_runtime.h>
#include <cstdint>

#define NSEQ 2048
#define SCALEQ 0.18033688011112042f   // (1/sqrt(64)) * log2(e)
#define NEGB (-1.0e30f)

// smem float offsets
#define QS    0        // 128 x 68
#define KS0   8704     // 64 x 68
#define KS1   13056
#define VS0   17408    // 64 x 72
#define VS1   22016
#define PS    26624    // 8 warps x (32 x 36)
#define MSK   35840    // 64 u32 mask bitwords
#define MPART 35904    // 2 x 128
#define LPART 36160    // 2 x 128
#define RMOF  36416    // 128
#define RROF  36544    // 128
#define SMEMF 36672    // floats (146,688 B)

static const size_t ATT_OFF = 2097152;   // 16*2048*64

__device__ __forceinline__ float ex2f_(float x) {
    float y; asm("ex2.approx.ftz.f32 %0, %1;" : "=f"(y) : "f"(x)); return y;
}
__device__ __forceinline__ unsigned cvt_tf32(float x) {
    unsigned y; asm("cvt.rna.tf32.f32 %0, %1;" : "=r"(y) : "f"(x)); return y;
}
__device__ __forceinline__ void mma_tf32(float c[4],
                                         unsigned a0, unsigned a1, unsigned a2, unsigned a3,
                                         unsigned b0, unsigned b1) {
    asm volatile(
        "mma.sync.aligned.m16n8k8.row.col.f32.tf32.tf32.f32 "
        "{%0,%1,%2,%3}, {%4,%5,%6,%7}, {%8,%9}, {%0,%1,%2,%3};"
        : "+f"(c[0]), "+f"(c[1]), "+f"(c[2]), "+f"(c[3])
        : "r"(a0), "r"(a1), "r"(a2), "r"(a3), "r"(b0), "r"(b1));
}

// ---- 64x64 tile LDG into registers (4 x float4 per thread) ----
__device__ __forceinline__ void ldg_tile(const float* __restrict__ src, float4 r[4], int tid) {
#pragma unroll
    for (int it = 0; it < 4; ++it) {
        int idx = tid + it * 256;
        int rr = idx >> 4, c4 = (idx & 15) << 2;
        r[it] = *(const float4*)(src + rr * 64 + c4);
    }
}
// ---- STS with tf32 convert, row stride SR floats ----
template <int SR>
__device__ __forceinline__ void sts_tile(float* dst, const float4 r[4], int tid) {
#pragma unroll
    for (int it = 0; it < 4; ++it) {
        int idx = tid + it * 256;
        int rr = idx >> 4, c4 = (idx & 15) << 2;
        uint4 u;
        u.x = cvt_tf32(r[it].x); u.y = cvt_tf32(r[it].y);
        u.z = cvt_tf32(r[it].z); u.w = cvt_tf32(r[it].w);
        *(uint4*)(dst + rr * SR + c4) = u;
    }
}

// S tile: Q A-fragments are register-resident (aq). Only K B-fragments hit smem.
__device__ __forceinline__ void compute_S(const unsigned aq[8][2][4], const float* __restrict__ Ks,
                                          int wn, int g, int tig, float c[2][4][4]) {
#pragma unroll
    for (int ms = 0; ms < 2; ++ms)
#pragma unroll
        for (int nt = 0; nt < 4; ++nt)
#pragma unroll
            for (int e = 0; e < 4; ++e) c[ms][nt][e] = 0.f;

#pragma unroll
    for (int ks = 0; ks < 8; ++ks) {
        int db = ks * 8;
#pragma unroll
        for (int nt = 0; nt < 4; ++nt) {
            const float* kr = Ks + (wn * 32 + nt * 8 + g) * 68 + db;
            unsigned b0 = __float_as_uint(kr[tig]);
            unsigned b1 = __float_as_uint(kr[tig + 4]);
            mma_tf32(c[0][nt], aq[ks][0][0], aq[ks][0][1], aq[ks][0][2], aq[ks][0][3], b0, b1);
            mma_tf32(c[1][nt], aq[ks][1][0], aq[ks][1][1], aq[ks][1][2], aq[ks][1][3], b0, b1);
        }
    }
}

__global__ void __launch_bounds__(256, 1)
lg3_kernel(const float* __restrict__ q, const float* __restrict__ k,
           const float* __restrict__ v, const int* __restrict__ mask,
           float* __restrict__ out) {
    extern __shared__ float sm[];
    const int tid = threadIdx.x;
    const int w = tid >> 5, lane = tid & 31;
    const int wm = w & 3, wn = w >> 2;
    const int g = lane >> 2, tig = lane & 3;

    const int bh = blockIdx.y, b = bh >> 2;     // H = 4
    const int i0 = blockIdx.x * 128;

    const float* qg = q + ((size_t)bh * NSEQ + i0) * 64;
    const float* kg = k + (size_t)bh * NSEQ * 64;
    const float* vg = v + (size_t)bh * NSEQ * 64;
    const int* mg = mask + (size_t)b * NSEQ;
    float* attg = out + ATT_OFF + ((size_t)bh * NSEQ + i0) * NSEQ;
    unsigned* mw = (unsigned*)(sm + MSK);

    // ---- prologue: Q (scaled, tf32) to smem; mask bitwords; K tile 0 ----
#pragma unroll
    for (int it = 0; it < 8; ++it) {
        int idx = tid + it * 256;
        int r = idx >> 4, c4 = (idx & 15) << 2;
        float4 t = *(const float4*)(qg + r * 64 + c4);
        uint4 u;
        u.x = cvt_tf32(t.x * SCALEQ); u.y = cvt_tf32(t.y * SCALEQ);
        u.z = cvt_tf32(t.z * SCALEQ); u.w = cvt_tf32(t.w * SCALEQ);
        *(uint4*)(sm + QS + r * 68 + c4) = u;
    }
    if (tid < 64) {
        unsigned bits = 0;
#pragma unroll 8
        for (int r = 0; r < 32; ++r) bits |= (mg[tid * 32 + r] != 0 ? 1u : 0u) << r;
        mw[tid] = bits;
    }
    {
        float4 pk[4];
        ldg_tile(kg, pk, tid);
        sts_tile<68>(sm + KS0, pk, tid);
    }
    __syncthreads();

    // ---- Q A-fragments: load once, keep in registers for all 64 tile-passes ----
    unsigned aq[8][2][4];
#pragma unroll
    for (int ks = 0; ks < 8; ++ks)
#pragma unroll
        for (int ms = 0; ms < 2; ++ms) {
            const float* qr = sm + QS + (wm * 32 + ms * 16 + g) * 68 + ks * 8;
            aq[ks][ms][0] = __float_as_uint(qr[tig]);
            aq[ks][ms][1] = __float_as_uint(qr[8 * 68 + tig]);
            aq[ks][ms][2] = __float_as_uint(qr[tig + 4]);
            aq[ks][ms][3] = __float_as_uint(qr[8 * 68 + tig + 4]);
        }

    // slot s (0..3): row = wm*32 + (s>>1)*16 + g + (s&1)*8
    float m[4], l[4];
#pragma unroll
    for (int s = 0; s < 4; ++s) { m[s] = NEGB; l[s] = 0.f; }

    // =================== Pass A: row max / sum ===================
    for (int j = 0; j < 32; ++j) {
        float4 pk[4];
        if (j < 31) ldg_tile(kg + (size_t)(j + 1) * 64 * 64, pk, tid);

        float c[2][4][4];
        compute_S(aq, sm + ((j & 1) ? KS1 : KS0), wn, g, tig, c);

        unsigned bits = mw[2 * j + wn];
        float tm[4] = {NEGB, NEGB, NEGB, NEGB};
#pragma unroll
        for (int ms = 0; ms < 2; ++ms)
#pragma unroll
            for (int nt = 0; nt < 4; ++nt)
#pragma unroll
                for (int e = 0; e < 4; ++e) {
                    int bit = nt * 8 + 2 * tig + (e & 1);
                    float s = ((bits >> bit) & 1u) ? c[ms][nt][e] : NEGB;
                    int slot = ms * 2 + (e >> 1);
                    tm[slot] = fmaxf(tm[slot], s);
                }
#pragma unroll
        for (int s = 0; s < 4; ++s) {
            float mn = fmaxf(m[s], tm[s]);
            l[s] *= ex2f_(m[s] - mn);
            m[s] = mn;
        }
#pragma unroll
        for (int ms = 0; ms < 2; ++ms)
#pragma unroll
            for (int nt = 0; nt < 4; ++nt)
#pragma unroll
                for (int e = 0; e < 4; ++e) {
                    int bit = nt * 8 + 2 * tig + (e & 1);
                    float s = ((bits >> bit) & 1u) ? c[ms][nt][e] : NEGB;
                    int slot = ms * 2 + (e >> 1);
                    l[slot] += ex2f_(s - m[slot]);
                }

        if (j < 31) sts_tile<68>(sm + (((j + 1) & 1) ? KS1 : KS0), pk, tid);
        __syncthreads();
    }

    // merge across the 4 lanes sharing each row, then across wn halves
#pragma unroll
    for (int s = 0; s < 4; ++s) {
#pragma unroll
        for (int off = 1; off <= 2; off <<= 1) {
            float mo = __shfl_xor_sync(0xffffffffu, m[s], off);
            float lo = __shfl_xor_sync(0xffffffffu, l[s], off);
            float mn = fmaxf(m[s], mo);
            l[s] = l[s] * ex2f_(m[s] - mn) + lo * ex2f_(mo - mn);
            m[s] = mn;
        }
    }
    if (tig == 0) {
#pragma unroll
        for (int s = 0; s < 4; ++s) {
            int row = wm * 32 + (s >> 1) * 16 + g + (s & 1) * 8;
            sm[MPART + wn * 128 + row] = m[s];
            sm[LPART + wn * 128 + row] = l[s];
        }
    }
    __syncthreads();
    if (tid < 128) {
        float ma = sm[MPART + tid], mb2 = sm[MPART + 128 + tid];
        float la = sm[LPART + tid], lb2 = sm[LPART + 128 + tid];
        float mn = fmaxf(ma, mb2);
        float lt = la * ex2f_(ma - mn) + lb2 * ex2f_(mb2 - mn);
        sm[RMOF + tid] = mn;
        sm[RROF + tid] = 1.0f / lt;
    }
    __syncthreads();

    float rm[4], rri[4];
#pragma unroll
    for (int s = 0; s < 4; ++s) {
        int row = wm * 32 + (s >> 1) * 16 + g + (s & 1) * 8;
        rm[s] = sm[RMOF + row];
        rri[s] = sm[RROF + row];
    }

    // =================== Pass B: P, attention store, O += P*V ===================
    float o[2][8][4];
#pragma unroll
    for (int ms = 0; ms < 2; ++ms)
#pragma unroll
        for (int nt = 0; nt < 8; ++nt)
#pragma unroll
            for (int e = 0; e < 4; ++e) o[ms][nt][e] = 0.f;

    {
        float4 pk[4], pv[4];
        ldg_tile(kg, pk, tid);
        ldg_tile(vg, pv, tid);
        sts_tile<68>(sm + KS0, pk, tid);
        sts_tile<72>(sm + VS0, pv, tid);
    }
    __syncthreads();

    float* Pw = sm + PS + w * (32 * 36);

    for (int j = 0; j < 32; ++j) {
        float4 pk[4], pv[4];
        if (j < 31) {
            ldg_tile(kg + (size_t)(j + 1) * 64 * 64, pk, tid);
            ldg_tile(vg + (size_t)(j + 1) * 64 * 64, pv, tid);
        }

        float c[2][4][4];
        compute_S(aq, sm + ((j & 1) ? KS1 : KS0), wn, g, tig, c);

        unsigned bits = mw[2 * j + wn];
        // fused epilogue: softmax -> attention STG -> P staging (tf32)
#pragma unroll
        for (int ms = 0; ms < 2; ++ms)
#pragma unroll
            for (int nt = 0; nt < 4; ++nt) {
                float p0, p1, p2, p3;
                {
                    int bit0 = nt * 8 + 2 * tig, bit1 = bit0 + 1;
                    float s0 = ((bits >> bit0) & 1u) ? c[ms][nt][0] : NEGB;
                    float s1 = ((bits >> bit1) & 1u) ? c[ms][nt][1] : NEGB;
                    float s2 = ((bits >> bit0) & 1u) ? c[ms][nt][2] : NEGB;
                    float s3 = ((bits >> bit1) & 1u) ? c[ms][nt][3] : NEGB;
                    int sl0 = ms * 2, sl1 = ms * 2 + 1;
                    p0 = ex2f_(s0 - rm[sl0]) * rri[sl0];
                    p1 = ex2f_(s1 - rm[sl0]) * rri[sl0];
                    p2 = ex2f_(s2 - rm[sl1]) * rri[sl1];
                    p3 = ex2f_(s3 - rm[sl1]) * rri[sl1];
                }
                int row = wm * 32 + ms * 16 + g;
                int col = j * 64 + wn * 32 + nt * 8 + 2 * tig;
                *(float2*)(attg + (size_t)row * NSEQ + col) = make_float2(p0, p1);
                *(float2*)(attg + (size_t)(row + 8) * NSEQ + col) = make_float2(p2, p3);

                int lr = ms * 16 + g, lc = nt * 8 + 2 * tig;
                *(uint2*)(Pw + lr * 36 + lc) = make_uint2(cvt_tf32(p0), cvt_tf32(p1));
                *(uint2*)(Pw + (lr + 8) * 36 + lc) = make_uint2(cvt_tf32(p2), cvt_tf32(p3));
            }
        __syncwarp();

        // O += P * V over this warp's 32 keys (split-k across wn)
        const float* Vs = sm + ((j & 1) ? VS1 : VS0);
#pragma unroll
        for (int kb = 0; kb < 4; ++kb) {
            unsigned a[2][4];
#pragma unroll
            for (int ms = 0; ms < 2; ++ms) {
                const float* pr = Pw + (ms * 16 + g) * 36 + kb * 8;
                a[ms][0] = __float_as_uint(pr[tig]);
                a[ms][1] = __float_as_uint(pr[8 * 36 + tig]);
                a[ms][2] = __float_as_uint(pr[tig + 4]);
                a[ms][3] = __float_as_uint(pr[8 * 36 + tig + 4]);
            }
            int krow = wn * 32 + kb * 8;
#pragma unroll
            for (int nt = 0; nt < 8; ++nt) {
                unsigned b0 = __float_as_uint(Vs[(krow + tig) * 72 + nt * 8 + g]);
                unsigned b1 = __float_as_uint(Vs[(krow + tig + 4) * 72 + nt * 8 + g]);
                mma_tf32(o[0][nt], a[0][0], a[0][1], a[0][2], a[0][3], b0, b1);
                mma_tf32(o[1][nt], a[1][0], a[1][1], a[1][2], a[1][3], b0, b1);
            }
        }

        if (j < 31) {
            sts_tile<68>(sm + (((j + 1) & 1) ? KS1 : KS0), pk, tid);
            sts_tile<72>(sm + (((j + 1) & 1) ? VS1 : VS0), pv, tid);
        }
        __syncthreads();
    }

    // ---- combine split-k halves of O and store ----
    __syncthreads();
    float* Os = sm + QS;   // Q region is dead now; stride 68
    if (wn == 1) {
#pragma unroll
        for (int ms = 0; ms < 2; ++ms)
#pragma unroll
            for (int nt = 0; nt < 8; ++nt) {
                int row = wm * 32 + ms * 16 + g, col = nt * 8 + 2 * tig;
                *(float2*)(Os + row * 68 + col) = make_float2(o[ms][nt][0], o[ms][nt][1]);
                *(float2*)(Os + (row + 8) * 68 + col) = make_float2(o[ms][nt][2], o[ms][nt][3]);
            }
    }
    __syncthreads();
    if (wn == 0) {
#pragma unroll
        for (int ms = 0; ms < 2; ++ms)
#pragma unroll
            for (int nt = 0; nt < 8; ++nt) {
                int row = wm * 32 + ms * 16 + g, col = nt * 8 + 2 * tig;
                float2 h0 = *(float2*)(Os + row * 68 + col);
                float2 h1 = *(float2*)(Os + (row + 8) * 68 + col);
                float* og0 = out + ((size_t)bh * NSEQ + i0 + row) * 64 + col;
                float* og1 = out + ((size_t)bh * NSEQ + i0 + row + 8) * 64 + col;
                *(float2*)og0 = make_float2(o[ms][nt][0] + h0.x, o[ms][nt][1] + h0.y);
                *(float2*)og1 = make_float2(o[ms][nt][2] + h1.x, o[ms][nt][3] + h1.y);
            }
    }
}

extern "C" void kernel_launch(void* const* d_in, const int* in_sizes, int n_in,
                              void* d_out, int out_size) {
    const float* q = (const float*)d_in[0];
    const float* k = (const float*)d_in[1];
    const float* v = (const float*)d_in[2];
    const int* mask = (const int*)d_in[3];
    float* out = (float*)d_out;

    const int smem_bytes = SMEMF * (int)sizeof(float);   // 146,688 B
    cudaFuncSetAttribute(lg3_kernel, cudaFuncAttributeMaxDynamicSharedMemorySize, smem_bytes);

    dim3 grid(NSEQ / 128, 16);
    lg3_kernel<<<grid, 256, smem_bytes>>>(q, k, v, mask, out);
}